// round 14
// baseline (speedup 1.0000x reference)
#include <cuda_runtime.h>
#include <cuda_fp16.h>
#include <math.h>

#define NTH 512
#define RPB 8

typedef unsigned long long ull;

// ---------------- packed weight scratch (device globals) ----
__device__ float  g_WrzT[2*256*256];   // float2 [i*256+o] = (Wr[o][i], Wz[o][i])
__device__ float  g_WnT [256*256];     // [i*256+o]
__device__ float  g_WihT[8*768];       // [ii*768+o]
__device__ float  g_e1P [256*256];     // "P" packing (pair {o,o+128})
__device__ float  g_e2mP[256*256];
__device__ float  g_e2sP[256*256];
// ODE weights fp16, thread-contiguous layout:
//   half index = ((i>>6)*128 + (o&127))*128 + (i&63)*2 + (o>>7)
//   -> thread (oc,q) owns 128 contiguous halves = 16 float4 loads
__device__ __half g_oWHv[4][65536];

__global__ void prep_kernel(const float* __restrict__ Wih, const float* __restrict__ Whh,
                            const float* __restrict__ eW1, const float* __restrict__ eW2,
                            const float* __restrict__ oW1, const float* __restrict__ oW2,
                            const float* __restrict__ oW3, const float* __restrict__ oW4)
{
    int idx = blockIdx.x*blockDim.x + threadIdx.x;
    if (idx >= 65536) return;
    int o = idx >> 8, i = idx & 255;
    ((float2*)g_WrzT)[i*256 + o] = make_float2(Whh[o*256 + i], Whh[(o+256)*256 + i]);
    g_WnT[i*256 + o] = Whh[(o+512)*256 + i];
    int pd = i*256 + ((o < 128) ? (2*o) : (2*(o-128) + 1));
    g_e1P [pd] = eW1[o*256 + i];
    g_e2mP[pd] = eW2[o*256 + i];
    g_e2sP[pd] = eW2[(o+256)*256 + i];
    int hv = ((i >> 6)*128 + (o & 127))*128 + (i & 63)*2 + (o >> 7);
    g_oWHv[0][hv] = __float2half_rn(oW1[o*256 + i]);
    g_oWHv[1][hv] = __float2half_rn(oW2[o*256 + i]);
    g_oWHv[2][hv] = __float2half_rn(oW3[o*256 + i]);
    g_oWHv[3][hv] = __float2half_rn(oW4[o*256 + i]);
    if (idx < 6144) { int oo = idx / 8, ii = idx % 8; g_WihT[ii*768 + oo] = Wih[idx]; }
}

// ---------------- f32x2 helpers ----------------
__device__ __forceinline__ ull pack2(float a, float b){
    ull r; asm("mov.b64 %0, {%1, %2};" : "=l"(r) : "f"(a), "f"(b)); return r;
}
__device__ __forceinline__ void unpack2(ull v, float& a, float& b){
    asm("mov.b64 {%0, %1}, %2;" : "=f"(a), "=f"(b) : "l"(v));
}
__device__ __forceinline__ void fma2(ull& acc, ull a, ull b){
    asm("fma.rn.f32x2 %0, %1, %2, %0;" : "+l"(acc) : "l"(a), "l"(b));
}

__device__ __forceinline__ float selu_f(float x){
    const float sc = 1.0507009873554805f;
    const float la = 1.7580993408473766f;   // lambda*alpha
    return x > 0.f ? sc*x : fmaf(la, __expf(x), -la);
}
__device__ __forceinline__ float sigmoid_f(float x){
    return 1.f/(1.f + __expf(-x));
}

// dopri5 coefficients
#define A21f 0.2f
#define A31f ((float)(3.0/40.0))
#define A32f ((float)(9.0/40.0))
#define A41f ((float)(44.0/45.0))
#define A42f ((float)(-56.0/15.0))
#define A43f ((float)(32.0/9.0))
#define A51f ((float)(19372.0/6561.0))
#define A52f ((float)(-25360.0/2187.0))
#define A53f ((float)(64448.0/6561.0))
#define A54f ((float)(-212.0/729.0))
#define A61f ((float)(9017.0/3168.0))
#define A62f ((float)(-355.0/33.0))
#define A63f ((float)(46732.0/5247.0))
#define A64f ((float)(49.0/176.0))
#define A65f ((float)(-5103.0/18656.0))
#define BC0f ((float)(35.0/384.0))
#define BC2f ((float)(500.0/1113.0))
#define BC3f ((float)(125.0/192.0))
#define BC4f ((float)(-2187.0/6784.0))
#define BC5f ((float)(11.0/84.0))
#define EC0f ((float)(35.0/384.0 - 5179.0/57600.0))
#define EC2f ((float)(500.0/1113.0 - 7571.0/16695.0))
#define EC3f ((float)(125.0/192.0 - 393.0/640.0))
#define EC4f ((float)(-2187.0/6784.0 + 92097.0/339200.0))
#define EC5f ((float)(11.0/84.0 - 187.0/2100.0))
#define EC6f ((float)(-1.0/40.0))

// SMEM plan (floats)
#define O_Y   0
#define O_TMP 2048
#define O_A   4096
#define O_B   6144
#define O_Y5  8192
#define O_K1  (5*2048)
#define O_K2  (6*2048)
#define O_K3  (7*2048)
#define O_K4  (8*2048)
#define O_K5  (9*2048)
#define O_K6  (10*2048)
#define O_PP  (11*2048)

// Activation layout (8 rows x 256 cols, 2048 floats):
//   elem (r, c) at buf[(r>>2)*1024 + c*4 + (r&3)]
// Split-K=4 matvec: thread (oc in [0,128), q in [0,4)) owns cols {oc, oc+128},
// all 8 rows, i in [q*64, q*64+64). Combine: thread owns float4 at tid*4.

// main accumulation, fp16 weights w/ vectorized contiguous stream
__device__ __forceinline__ float4 mv4h_main(const __half* __restrict__ WT,
                                            const float* __restrict__ bias,
                                            const float* __restrict__ inT,
                                            float* __restrict__ Pp,
                                            int oc, int q, int tid)
{
    const float4* in4 = (const float4*)inT;
    const float4* wvp = (const float4*)(WT + (q*128 + oc)*128);
    ull a00=0,a01=0,a02=0,a03=0;
    ull a10=0,a11=0,a12=0,a13=0;
#pragma unroll
    for (int jj = 0; jj < 16; jj++) {
        float4 wq = __ldg(wvp + jj);
        const __half2* wh = (const __half2*)&wq;
#pragma unroll
        for (int k = 0; k < 4; k++) {
            int i = q*64 + jj*4 + k;
            float2 w = __half22float2(wh[k]);
            float4 u0 = in4[i];
            float4 u1 = in4[256 + i];
            ull p0 = pack2(u0.x,u0.y), p1 = pack2(u0.z,u0.w);
            ull p2 = pack2(u1.x,u1.y), p3 = pack2(u1.z,u1.w);
            ull wx = pack2(w.x,w.x), wy = pack2(w.y,w.y);
            fma2(a00,p0,wx); fma2(a01,p1,wx); fma2(a02,p2,wx); fma2(a03,p3,wx);
            fma2(a10,p0,wy); fma2(a11,p1,wy); fma2(a12,p2,wy); fma2(a13,p3,wy);
        }
    }
    float* P = Pp + q*2048;
    float f0,f1,f2,f3;
    unpack2(a00,f0,f1); unpack2(a01,f2,f3); *(float4*)(P + oc*4)        = make_float4(f0,f1,f2,f3);
    unpack2(a10,f0,f1); unpack2(a11,f2,f3); *(float4*)(P + 512 + oc*4)  = make_float4(f0,f1,f2,f3);
    unpack2(a02,f0,f1); unpack2(a03,f2,f3); *(float4*)(P + 1024 + oc*4) = make_float4(f0,f1,f2,f3);
    unpack2(a12,f0,f1); unpack2(a13,f2,f3); *(float4*)(P + 1536 + oc*4) = make_float4(f0,f1,f2,f3);
    __syncthreads();
    const int e4 = tid*4;
    float4 s0 = *(float4*)(Pp + e4);
    float4 s1 = *(float4*)(Pp + 2048 + e4);
    float4 s2 = *(float4*)(Pp + 4096 + e4);
    float4 s3 = *(float4*)(Pp + 6144 + e4);
    float b = __ldg(bias + (tid & 255));
    return make_float4(s0.x+s1.x+s2.x+s3.x+b, s0.y+s1.y+s2.y+s3.y+b,
                       s0.z+s1.z+s2.z+s3.z+b, s0.w+s1.w+s2.w+s3.w+b);
}

// plain layer (selu) -> outT
__device__ __noinline__ void mv4h_selu(const __half* __restrict__ WT,
                                       const float* __restrict__ bias,
                                       const float* __restrict__ inT,
                                       float* __restrict__ outT,
                                       float* __restrict__ Pp,
                                       int oc, int q, int tid)
{
    float4 v = mv4h_main(WT, bias, inT, Pp, oc, q, tid);
    v.x = selu_f(v.x); v.y = selu_f(v.y); v.z = selu_f(v.z); v.w = selu_f(v.w);
    *(float4*)(outT + tid*4) = v;
    __syncthreads();
}

// final ODE layer with fused stage epilogue. epi in [1,7].
__device__ __noinline__ void mv4h_last(const __half* __restrict__ WT,
                                       const float* __restrict__ bias,
                                       const float* __restrict__ inT,
                                       float* __restrict__ outT,
                                       float* __restrict__ sm,
                                       int oc, int q, int tid, int epi, float4 dv)
{
    float* Pp = sm + O_PP;
    float4 v = mv4h_main(WT, bias, inT, Pp, oc, q, tid);
    const int e4 = tid*4;
    *(float4*)(outT + e4) = v;
    float4 y = *(float4*)(sm + O_Y + e4);
#define PER4(DST, EX) do { float4 _o; _o.x=EX(x); _o.y=EX(y); _o.z=EX(z); _o.w=EX(w); \
                           *(float4*)(DST + e4) = _o; } while(0)
    if (epi == 1) {
#define S1(c) fmaf(dv.c, A21f*v.c, y.c)
        PER4(sm + O_TMP, S1);
#undef S1
    } else if (epi == 2) {
        float4 k1 = *(float4*)(sm + O_K1 + e4);
#define S2(c) fmaf(dv.c, A31f*k1.c + A32f*v.c, y.c)
        PER4(sm + O_TMP, S2);
#undef S2
    } else if (epi == 3) {
        float4 k1 = *(float4*)(sm + O_K1 + e4);
        float4 k2 = *(float4*)(sm + O_K2 + e4);
#define S3(c) fmaf(dv.c, A41f*k1.c + A42f*k2.c + A43f*v.c, y.c)
        PER4(sm + O_TMP, S3);
#undef S3
    } else if (epi == 4) {
        float4 k1 = *(float4*)(sm + O_K1 + e4);
        float4 k2 = *(float4*)(sm + O_K2 + e4);
        float4 k3 = *(float4*)(sm + O_K3 + e4);
#define S4(c) fmaf(dv.c, A51f*k1.c + A52f*k2.c + A53f*k3.c + A54f*v.c, y.c)
        PER4(sm + O_TMP, S4);
#undef S4
    } else if (epi == 5) {
        float4 k1 = *(float4*)(sm + O_K1 + e4);
        float4 k2 = *(float4*)(sm + O_K2 + e4);
        float4 k3 = *(float4*)(sm + O_K3 + e4);
        float4 k4 = *(float4*)(sm + O_K4 + e4);
#define S5(c) fmaf(dv.c, A61f*k1.c + A62f*k2.c + A63f*k3.c + A64f*k4.c + A65f*v.c, y.c)
        PER4(sm + O_TMP, S5);
#undef S5
    } else if (epi == 6) {
        float4 k1 = *(float4*)(sm + O_K1 + e4);
        float4 k3 = *(float4*)(sm + O_K3 + e4);
        float4 k4 = *(float4*)(sm + O_K4 + e4);
        float4 k5 = *(float4*)(sm + O_K5 + e4);
#define S6(c) fmaf(dv.c, BC0f*k1.c + BC2f*k3.c + BC3f*k4.c + BC4f*k5.c + BC5f*v.c, y.c)
        PER4(sm + O_Y5, S6);
#undef S6
    } else {   // epi == 7: error contributions -> red (== aT)
        float4 k1 = *(float4*)(sm + O_K1 + e4);
        float4 k3 = *(float4*)(sm + O_K3 + e4);
        float4 k4 = *(float4*)(sm + O_K4 + e4);
        float4 k5 = *(float4*)(sm + O_K5 + e4);
        float4 k6 = *(float4*)(sm + O_K6 + e4);
        float4 y5 = *(float4*)(sm + O_Y5 + e4);
#define S7(c) ({ float _e = EC0f*k1.c + EC2f*k3.c + EC3f*k4.c + EC4f*k5.c + EC5f*k6.c + EC6f*v.c; \
                 float _q = dv.c*_e / (1e-6f + 1e-3f*fmaxf(fabsf(y.c), fabsf(y5.c))); _q*_q; })
        PER4(sm + O_A, S7);
#undef S7
    }
#undef PER4
    __syncthreads();
}

__device__ __noinline__ void feval_fused(float* __restrict__ sm,
                                         const float* __restrict__ inT,
                                         float* __restrict__ outT,
                                         const float* ob1, const float* ob2,
                                         const float* ob3, const float* ob4,
                                         int oc, int q, int tid, int epi, float4 dv)
{
    float* Pp = sm + O_PP;
    mv4h_selu(g_oWHv[0], ob1, inT, sm + O_A, Pp, oc, q, tid);
    mv4h_selu(g_oWHv[1], ob2, sm + O_A, sm + O_B, Pp, oc, q, tid);
    mv4h_selu(g_oWHv[2], ob3, sm + O_B, sm + O_A, Pp, oc, q, tid);
    mv4h_last(g_oWHv[3], ob4, sm + O_A, outT, sm, oc, q, tid, epi, dv);
}

// fp32-weight matvec (encoder), act: 0 none, 2 relu
__device__ __noinline__ void mv4f(const float* __restrict__ WT,
                                  const float* __restrict__ bias,
                                  const float* __restrict__ inT,
                                  float* __restrict__ outT,
                                  float* __restrict__ Pp,
                                  int oc, int q, int tid, int act)
{
    const float4* in4 = (const float4*)inT;
    const float2* w2p = (const float2*)WT + q*64*128 + oc;
    ull a00=0,a01=0,a02=0,a03=0;
    ull a10=0,a11=0,a12=0,a13=0;
#pragma unroll 8
    for (int ii = 0; ii < 64; ii++) {
        int i = q*64 + ii;
        float2 w = __ldg(w2p + ii*128);
        float4 u0 = in4[i];
        float4 u1 = in4[256 + i];
        ull p0 = pack2(u0.x,u0.y), p1 = pack2(u0.z,u0.w);
        ull p2 = pack2(u1.x,u1.y), p3 = pack2(u1.z,u1.w);
        ull wx = pack2(w.x,w.x), wy = pack2(w.y,w.y);
        fma2(a00,p0,wx); fma2(a01,p1,wx); fma2(a02,p2,wx); fma2(a03,p3,wx);
        fma2(a10,p0,wy); fma2(a11,p1,wy); fma2(a12,p2,wy); fma2(a13,p3,wy);
    }
    float* P = Pp + q*2048;
    float f0,f1,f2,f3;
    unpack2(a00,f0,f1); unpack2(a01,f2,f3); *(float4*)(P + oc*4)        = make_float4(f0,f1,f2,f3);
    unpack2(a10,f0,f1); unpack2(a11,f2,f3); *(float4*)(P + 512 + oc*4)  = make_float4(f0,f1,f2,f3);
    unpack2(a02,f0,f1); unpack2(a03,f2,f3); *(float4*)(P + 1024 + oc*4) = make_float4(f0,f1,f2,f3);
    unpack2(a12,f0,f1); unpack2(a13,f2,f3); *(float4*)(P + 1536 + oc*4) = make_float4(f0,f1,f2,f3);
    __syncthreads();
    const int e4 = tid*4;
    float4 s0 = *(float4*)(Pp + e4);
    float4 s1 = *(float4*)(Pp + 2048 + e4);
    float4 s2 = *(float4*)(Pp + 4096 + e4);
    float4 s3 = *(float4*)(Pp + 6144 + e4);
    float b = __ldg(bias + (tid & 255));
    float4 v = make_float4(s0.x+s1.x+s2.x+s3.x+b, s0.y+s1.y+s2.y+s3.y+b,
                           s0.z+s1.z+s2.z+s3.z+b, s0.w+s1.w+s2.w+s3.w+b);
    if (act == 2) { v.x=fmaxf(v.x,0.f); v.y=fmaxf(v.y,0.f); v.z=fmaxf(v.z,0.f); v.w=fmaxf(v.w,0.f); }
    *(float4*)(outT + e4) = v;
    __syncthreads();
}

// ---------------- main persistent kernel ----------------
__global__ __launch_bounds__(NTH, 1)
void node_kernel(const float* __restrict__ x,     const float* __restrict__ meta,
                 const float* __restrict__ eps,   const float* __restrict__ times,
                 const float* __restrict__ doses,
                 const float* __restrict__ gbih,  const float* __restrict__ gbhh,
                 const float* __restrict__ eb1,   const float* __restrict__ eb2,
                 const float* __restrict__ ob1,   const float* __restrict__ ob2,
                 const float* __restrict__ ob3,   const float* __restrict__ ob4,
                 const float* __restrict__ fcW,   const float* __restrict__ fcb,
                 float* __restrict__ out)
{
    extern __shared__ float sm[];
    float* yT   = sm + O_Y;
    float* tmpT = sm + O_TMP;
    float* red  = sm + O_A;      // aT doubles as error buffer
    float* y5T  = sm + O_Y5;
    float* k1T  = sm + O_K1;     // x cache during GRU
    float* Pp   = sm + O_PP;     // split-K partials / GRU gate planes
    float* xc   = k1T;

    __shared__ float t_s[8], t1_s[8], dt_s[8], d_s[8], ds_s[8], meta_s[32];
    __shared__ int   act_s[8], accfl[8];

    const int tid  = threadIdx.x;
    const int oc   = tid & 127;      // ODE: column pair {oc, oc+128}
    const int q    = tid >> 7;       // ODE: K-chunk 0..3
    const int o    = tid & 255;      // GRU: column
    const int qg   = tid >> 8;       // GRU: 0 -> r,z ; 1 -> n
    const int wid  = tid >> 5;
    const int lane = tid & 31;
    const int r0   = blockIdx.x * RPB;
    const int e4   = tid*4;          // my float4 in [0,2048)
    const int hh   = tid >> 8;       // my row block: rows 4hh..4hh+3
    const int rb   = hh*4;

    for (int e = tid; e < 2048; e += NTH) { xc[e] = x[r0*256 + e]; yT[e] = 0.f; }
    if (tid < 32) meta_s[tid] = meta[r0*4 + tid];

    // GRU register weights / biases
    float wA[8], wB[8];
    float bA, bB, bN = 0.f;
    if (qg == 0) {
#pragma unroll
        for (int c = 0; c < 8; c++) { wA[c] = g_WihT[c*768 + o]; wB[c] = g_WihT[c*768 + o + 256]; }
        bA = gbih[o] + gbhh[o];
        bB = gbih[o+256] + gbhh[o+256];
    } else {
#pragma unroll
        for (int c = 0; c < 8; c++) { wA[c] = g_WihT[c*768 + o + 512]; wB[c] = 0.f; }
        bA = gbhh[o + 512];
        bN = gbih[o + 512];
        bB = 0.f;
    }
    __syncthreads();

    // ---------------- Phase A: GRU over 64 timesteps ----------------
    for (int t = 0; t < 64; t++) {
        if (qg == 0) {
            ull ar0 = pack2(bA,bA), ar1 = ar0, ar2 = ar0, ar3 = ar0;
            ull az0 = pack2(bB,bB), az1 = az0, az2 = az0, az3 = az0;
            const float2* wrz = (const float2*)g_WrzT + o;
            const float4* h4 = (const float4*)yT;
#pragma unroll 8
            for (int i = 0; i < 256; i++) {
                float2 w = __ldg(wrz + i*256);
                float4 u0 = h4[i];
                float4 u1 = h4[256 + i];
                ull p0 = pack2(u0.x,u0.y), p1 = pack2(u0.z,u0.w);
                ull p2 = pack2(u1.x,u1.y), p3 = pack2(u1.z,u1.w);
                ull wx = pack2(w.x,w.x), wy = pack2(w.y,w.y);
                fma2(ar0,p0,wx); fma2(ar1,p1,wx); fma2(ar2,p2,wx); fma2(ar3,p3,wx);
                fma2(az0,p0,wy); fma2(az1,p1,wy); fma2(az2,p2,wy); fma2(az3,p3,wy);
            }
            float fr[8], fz[8];
            unpack2(ar0,fr[0],fr[1]); unpack2(ar1,fr[2],fr[3]);
            unpack2(ar2,fr[4],fr[5]); unpack2(ar3,fr[6],fr[7]);
            unpack2(az0,fz[0],fz[1]); unpack2(az1,fz[2],fz[3]);
            unpack2(az2,fz[4],fz[5]); unpack2(az3,fz[6],fz[7]);
#pragma unroll
            for (int r = 0; r < 8; r++) {
                float sr = 0.f, sz = 0.f;
#pragma unroll
                for (int c = 0; c < 4; c++) {
                    float xv = xc[r*256 + t*4 + c];
                    sr = fmaf(xv, wA[c], sr); sz = fmaf(xv, wB[c], sz);
                }
#pragma unroll
                for (int c = 0; c < 4; c++) {
                    float mv = meta_s[r*4 + c];
                    sr = fmaf(mv, wA[4+c], sr); sz = fmaf(mv, wB[4+c], sz);
                }
                fr[r] = sigmoid_f(fr[r] + sr);
                fz[r] = sigmoid_f(fz[r] + sz);
            }
            *(float4*)(Pp + o*4)        = make_float4(fr[0],fr[1],fr[2],fr[3]);
            *(float4*)(Pp + 1024 + o*4) = make_float4(fr[4],fr[5],fr[6],fr[7]);
            *(float4*)(Pp + 2048 + o*4) = make_float4(fz[0],fz[1],fz[2],fz[3]);
            *(float4*)(Pp + 3072 + o*4) = make_float4(fz[4],fz[5],fz[6],fz[7]);
            __syncthreads();
            __syncthreads();
        } else {
            ull an0 = pack2(bA,bA), an1 = an0, an2 = an0, an3 = an0;
            const float* wn = g_WnT + o;
            const float4* h4 = (const float4*)yT;
#pragma unroll 8
            for (int i = 0; i < 256; i++) {
                float w = __ldg(wn + i*256);
                float4 u0 = h4[i];
                float4 u1 = h4[256 + i];
                ull w2 = pack2(w,w);
                fma2(an0, pack2(u0.x,u0.y), w2);
                fma2(an1, pack2(u0.z,u0.w), w2);
                fma2(an2, pack2(u1.x,u1.y), w2);
                fma2(an3, pack2(u1.z,u1.w), w2);
            }
            float hn[8];
            unpack2(an0,hn[0],hn[1]); unpack2(an1,hn[2],hn[3]);
            unpack2(an2,hn[4],hn[5]); unpack2(an3,hn[6],hn[7]);
            float inn[8];
#pragma unroll
            for (int r = 0; r < 8; r++) {
                float s = bN;
#pragma unroll
                for (int c = 0; c < 4; c++) s = fmaf(xc[r*256 + t*4 + c], wA[c], s);
#pragma unroll
                for (int c = 0; c < 4; c++) s = fmaf(meta_s[r*4 + c], wA[4+c], s);
                inn[r] = s;
            }
            __syncthreads();
            float4 R0 = *(float4*)(Pp + o*4);
            float4 R1 = *(float4*)(Pp + 1024 + o*4);
            float4 Z0 = *(float4*)(Pp + 2048 + o*4);
            float4 Z1 = *(float4*)(Pp + 3072 + o*4);
            float4 h0 = *(float4*)(yT + o*4);
            float4 h1 = *(float4*)(yT + 1024 + o*4);
            float Rr[8] = {R0.x,R0.y,R0.z,R0.w,R1.x,R1.y,R1.z,R1.w};
            float Zr[8] = {Z0.x,Z0.y,Z0.z,Z0.w,Z1.x,Z1.y,Z1.z,Z1.w};
            float hr[8] = {h0.x,h0.y,h0.z,h0.w,h1.x,h1.y,h1.z,h1.w};
            float hnew[8];
#pragma unroll
            for (int r = 0; r < 8; r++) {
                float n = tanhf(inn[r] + Rr[r]*hn[r]);
                hnew[r] = (1.f - Zr[r])*n + Zr[r]*hr[r];
            }
            *(float4*)(yT + o*4)        = make_float4(hnew[0],hnew[1],hnew[2],hnew[3]);
            *(float4*)(yT + 1024 + o*4) = make_float4(hnew[4],hnew[5],hnew[6],hnew[7]);
            __syncthreads();
        }
    }

    // ---------------- Phase B: encoder -> y0 ----------------
    mv4f(g_e1P,  eb1,       yT,          sm + O_B,  Pp, oc, q, tid, 2);  // relu
    mv4f(g_e2mP, eb2,       sm + O_B,    sm + O_A,  Pp, oc, q, tid, 0);  // mean
    mv4f(g_e2sP, eb2 + 256, sm + O_B,    y5T,       Pp, oc, q, tid, 0);  // std
    {
        int c = tid & 255;
        float4 m = *(float4*)(sm + O_A + e4);
        float4 s = *(float4*)(y5T + e4);
        float4 y0;
        y0.x = fmaf(__ldg(eps + (r0 + rb + 0)*256 + c), s.x, m.x);
        y0.y = fmaf(__ldg(eps + (r0 + rb + 1)*256 + c), s.y, m.y);
        y0.z = fmaf(__ldg(eps + (r0 + rb + 2)*256 + c), s.z, m.z);
        y0.w = fmaf(__ldg(eps + (r0 + rb + 3)*256 + c), s.w, m.w);
        *(float4*)(yT + e4) = y0;
    }
    __syncthreads();

    // ---------------- Phase C: 4 x dopri5 (FSAL + fused epilogues) --------
    for (int j = 0; j < 4; j++) {
        if (tid < 8) {
            int row = r0 + tid;
            float t0v = times[(j*1024 + row)*2 + 0];
            float t1v = times[(j*1024 + row)*2 + 1];
            t_s[tid]  = t0v;
            t1_s[tid] = t1v;
            dt_s[tid] = fmaxf(t1v - t0v, 1e-6f) * 0.1f;
            ds_s[tid] = (t0v < t1v) ? doses[j*1024 + row] : 0.f;
        }
        __syncthreads();
        {
            float4 y = *(float4*)(yT + e4);
            y.x += ds_s[rb+0]; y.y += ds_s[rb+1]; y.z += ds_s[rb+2]; y.w += ds_s[rb+3];
            *(float4*)(yT + e4) = y;
        }

        int fsal = 0;
        for (int step = 0; step < 32; step++) {
            int myact = 0;
            if (tid < 8) {
                float tt = t_s[tid], t1v = t1_s[tid];
                myact = (tt < t1v) ? 1 : 0;
                act_s[tid] = myact;
                float rem = fmaxf(t1v - tt, 0.f);
                d_s[tid] = fminf(fmaxf(dt_s[tid], 0.f), rem);
            }
            if (!__syncthreads_or(myact)) break;   // uniform exit

            const float4 dv = make_float4(d_s[rb+0], d_s[rb+1], d_s[rb+2], d_s[rb+3]);

            if (fsal) {
                // k1 select (exact FSAL) + stage-1 combine
                float4 kp  = *(float4*)(k1T + e4);
                float4 k7v = *(float4*)(tmpT + e4);
                if (accfl[rb+0]) kp.x = k7v.x;
                if (accfl[rb+1]) kp.y = k7v.y;
                if (accfl[rb+2]) kp.z = k7v.z;
                if (accfl[rb+3]) kp.w = k7v.w;
                *(float4*)(k1T + e4) = kp;
                float4 y = *(float4*)(yT + e4);
                float4 tt;
                tt.x = fmaf(dv.x, A21f*kp.x, y.x);
                tt.y = fmaf(dv.y, A21f*kp.y, y.y);
                tt.z = fmaf(dv.z, A21f*kp.z, y.z);
                tt.w = fmaf(dv.w, A21f*kp.w, y.w);
                *(float4*)(tmpT + e4) = tt;
                __syncthreads();
            } else {
                feval_fused(sm, yT, k1T, ob1, ob2, ob3, ob4, oc, q, tid, 1, dv);
            }
            feval_fused(sm, tmpT, sm + O_K2, ob1, ob2, ob3, ob4, oc, q, tid, 2, dv);
            feval_fused(sm, tmpT, sm + O_K3, ob1, ob2, ob3, ob4, oc, q, tid, 3, dv);
            feval_fused(sm, tmpT, sm + O_K4, ob1, ob2, ob3, ob4, oc, q, tid, 4, dv);
            feval_fused(sm, tmpT, sm + O_K5, ob1, ob2, ob3, ob4, oc, q, tid, 5, dv);
            feval_fused(sm, tmpT, sm + O_K6, ob1, ob2, ob3, ob4, oc, q, tid, 6, dv);  // -> y5T
            feval_fused(sm, y5T,  tmpT,     ob1, ob2, ob3, ob4, oc, q, tid, 7, dv);  // k7 + err->red

            if (wid < 8) {
                int r = wid;
                const float* rp = red + ((r>>2)<<10) + (r&3);
                float s = 0.f;
#pragma unroll
                for (int c = 0; c < 8; c++) s += rp[(lane + 32*c)*4];
                s += __shfl_xor_sync(0xffffffffu, s, 16);
                s += __shfl_xor_sync(0xffffffffu, s, 8);
                s += __shfl_xor_sync(0xffffffffu, s, 4);
                s += __shfl_xor_sync(0xffffffffu, s, 2);
                s += __shfl_xor_sync(0xffffffffu, s, 1);
                if (lane == 0) {
                    float en = sqrtf(s * (1.f/256.f));
                    int active = act_s[r];
                    int acc = (en <= 1.f) && active;
                    accfl[r] = acc;
                    float dtc = d_s[r];
                    if (acc) t_s[r] += dtc;
                    if (active) {
                        float fac = 0.9f * __expf(-0.2f * __logf(en + 1e-10f));
                        fac = fminf(fmaxf(fac, 0.2f), 10.f);
                        dt_s[r] = fmaxf(dtc, 1e-8f) * fac;
                    }
                }
            }
            __syncthreads();
            {
                float4 y  = *(float4*)(yT + e4);
                float4 y5 = *(float4*)(y5T + e4);
                if (accfl[rb+0]) y.x = y5.x;
                if (accfl[rb+1]) y.y = y5.y;
                if (accfl[rb+2]) y.z = y5.z;
                if (accfl[rb+3]) y.w = y5.w;
                *(float4*)(yT + e4) = y;
            }
            __syncthreads();
            fsal = 1;
        }
    }

    // ---------------- Phase D: linear head ----------------
    {
        float fcw = __ldg(fcW + (tid & 255));
        float4 y = *(float4*)(yT + e4);
        *(float4*)(red + e4) = make_float4(y.x*fcw, y.y*fcw, y.z*fcw, y.w*fcw);
        __syncthreads();
        if (wid < 8) {
            int r = wid;
            const float* rp = red + ((r>>2)<<10) + (r&3);
            float s = 0.f;
#pragma unroll
            for (int c = 0; c < 8; c++) s += rp[(lane + 32*c)*4];
            s += __shfl_xor_sync(0xffffffffu, s, 16);
            s += __shfl_xor_sync(0xffffffffu, s, 8);
            s += __shfl_xor_sync(0xffffffffu, s, 4);
            s += __shfl_xor_sync(0xffffffffu, s, 2);
            s += __shfl_xor_sync(0xffffffffu, s, 1);
            if (lane == 0) {
                s += fcb[0];
#pragma unroll
                for (int c = 0; c < 4; c++) s += meta_s[r*4 + c] * fcW[256 + c];
                out[r0 + r] = s;
            }
        }
    }
}

extern "C" void kernel_launch(void* const* d_in, const int* in_sizes, int n_in,
                              void* d_out, int out_size)
{
    const float* x     = (const float*)d_in[0];
    const float* meta  = (const float*)d_in[1];
    const float* eps   = (const float*)d_in[2];
    const float* times = (const float*)d_in[3];
    const float* doses = (const float*)d_in[4];
    const float* gWih  = (const float*)d_in[5];
    const float* gWhh  = (const float*)d_in[6];
    const float* gbih  = (const float*)d_in[7];
    const float* gbhh  = (const float*)d_in[8];
    const float* eW1   = (const float*)d_in[9];
    const float* eb1   = (const float*)d_in[10];
    const float* eW2   = (const float*)d_in[11];
    const float* eb2   = (const float*)d_in[12];
    const float* oW1   = (const float*)d_in[13];
    const float* ob1   = (const float*)d_in[14];
    const float* oW2   = (const float*)d_in[15];
    const float* ob2   = (const float*)d_in[16];
    const float* oW3   = (const float*)d_in[17];
    const float* ob3   = (const float*)d_in[18];
    const float* oW4   = (const float*)d_in[19];
    const float* ob4   = (const float*)d_in[20];
    const float* fcW   = (const float*)d_in[21];
    const float* fcb   = (const float*)d_in[22];
    float* out = (float*)d_out;

    prep_kernel<<<256, 256>>>(gWih, gWhh, eW1, eW2, oW1, oW2, oW3, oW4);

    const int smem_bytes = (11*2048 + 4*2048) * sizeof(float);   // 122880
    static int attr_done = 0;
    if (!attr_done) {
        cudaFuncSetAttribute(node_kernel, cudaFuncAttributeMaxDynamicSharedMemorySize, smem_bytes);
        attr_done = 1;
    }
    node_kernel<<<128, NTH, smem_bytes>>>(x, meta, eps, times, doses,
                                          gbih, gbhh, eb1, eb2,
                                          ob1, ob2, ob3, ob4, fcW, fcb, out);
}

// round 15
// speedup vs baseline: 1.5452x; 1.5452x over previous
#include <cuda_runtime.h>
#include <cuda_fp16.h>
#include <math.h>

#define NTH 512
#define RPB 8

typedef unsigned long long ull;

// ---------------- packed weight scratch (device globals) ----
__device__ float  g_WrzT[2*256*256];   // float2 [i*256+o] = (Wr[o][i], Wz[o][i])
__device__ float  g_WnT [256*256];     // [i*256+o]
__device__ float  g_WihT[8*768];       // [ii*768+o]
__device__ float  g_e1P [256*256];     // "P" packing (pair {o,o+128})
__device__ float  g_e2mP[256*256];
__device__ float  g_e2sP[256*256];
// ODE weights fp16, i-vectorized + lane-coalesced layout:
//   for output pair (oc, oc+128), K-chunk q, sub-block jj=(i&63)>>2, par=i&3:
//   half index = (((i>>6)*16 + ((i&63)>>2))*128 + (o&127))*8 + (i&3)*2 + (o>>7)
//   -> one float4 = 4 consecutive i for both columns; lanes oc adjacent -> 16B apart.
__device__ __half g_oWHv[4][65536];

__global__ void prep_kernel(const float* __restrict__ Wih, const float* __restrict__ Whh,
                            const float* __restrict__ eW1, const float* __restrict__ eW2,
                            const float* __restrict__ oW1, const float* __restrict__ oW2,
                            const float* __restrict__ oW3, const float* __restrict__ oW4)
{
    int idx = blockIdx.x*blockDim.x + threadIdx.x;
    if (idx >= 65536) return;
    int o = idx >> 8, i = idx & 255;
    ((float2*)g_WrzT)[i*256 + o] = make_float2(Whh[o*256 + i], Whh[(o+256)*256 + i]);
    g_WnT[i*256 + o] = Whh[(o+512)*256 + i];
    int pd = i*256 + ((o < 128) ? (2*o) : (2*(o-128) + 1));
    g_e1P [pd] = eW1[o*256 + i];
    g_e2mP[pd] = eW2[o*256 + i];
    g_e2sP[pd] = eW2[(o+256)*256 + i];
    int hv = (((i >> 6)*16 + ((i & 63) >> 2))*128 + (o & 127))*8 + (i & 3)*2 + (o >> 7);
    g_oWHv[0][hv] = __float2half_rn(oW1[o*256 + i]);
    g_oWHv[1][hv] = __float2half_rn(oW2[o*256 + i]);
    g_oWHv[2][hv] = __float2half_rn(oW3[o*256 + i]);
    g_oWHv[3][hv] = __float2half_rn(oW4[o*256 + i]);
    if (idx < 6144) { int oo = idx / 8, ii = idx % 8; g_WihT[ii*768 + oo] = Wih[idx]; }
}

// ---------------- f32x2 helpers ----------------
__device__ __forceinline__ ull pack2(float a, float b){
    ull r; asm("mov.b64 %0, {%1, %2};" : "=l"(r) : "f"(a), "f"(b)); return r;
}
__device__ __forceinline__ void unpack2(ull v, float& a, float& b){
    asm("mov.b64 {%0, %1}, %2;" : "=f"(a), "=f"(b) : "l"(v));
}
__device__ __forceinline__ void fma2(ull& acc, ull a, ull b){
    asm("fma.rn.f32x2 %0, %1, %2, %0;" : "+l"(acc) : "l"(a), "l"(b));
}

__device__ __forceinline__ float selu_f(float x){
    const float sc = 1.0507009873554805f;
    const float la = 1.7580993408473766f;   // lambda*alpha
    return x > 0.f ? sc*x : fmaf(la, __expf(x), -la);
}
__device__ __forceinline__ float sigmoid_f(float x){
    return 1.f/(1.f + __expf(-x));
}

// dopri5 coefficients
#define A21f 0.2f
#define A31f ((float)(3.0/40.0))
#define A32f ((float)(9.0/40.0))
#define A41f ((float)(44.0/45.0))
#define A42f ((float)(-56.0/15.0))
#define A43f ((float)(32.0/9.0))
#define A51f ((float)(19372.0/6561.0))
#define A52f ((float)(-25360.0/2187.0))
#define A53f ((float)(64448.0/6561.0))
#define A54f ((float)(-212.0/729.0))
#define A61f ((float)(9017.0/3168.0))
#define A62f ((float)(-355.0/33.0))
#define A63f ((float)(46732.0/5247.0))
#define A64f ((float)(49.0/176.0))
#define A65f ((float)(-5103.0/18656.0))
#define BC0f ((float)(35.0/384.0))
#define BC2f ((float)(500.0/1113.0))
#define BC3f ((float)(125.0/192.0))
#define BC4f ((float)(-2187.0/6784.0))
#define BC5f ((float)(11.0/84.0))
#define EC0f ((float)(35.0/384.0 - 5179.0/57600.0))
#define EC2f ((float)(500.0/1113.0 - 7571.0/16695.0))
#define EC3f ((float)(125.0/192.0 - 393.0/640.0))
#define EC4f ((float)(-2187.0/6784.0 + 92097.0/339200.0))
#define EC5f ((float)(11.0/84.0 - 187.0/2100.0))
#define EC6f ((float)(-1.0/40.0))

// SMEM plan (floats)
#define O_Y   0
#define O_TMP 2048
#define O_A   4096
#define O_B   6144
#define O_Y5  8192
#define O_K1  (5*2048)
#define O_K2  (6*2048)
#define O_K3  (7*2048)
#define O_K4  (8*2048)
#define O_K5  (9*2048)
#define O_K6  (10*2048)
#define O_PP  (11*2048)

// Activation layout (8 rows x 256 cols, 2048 floats):
//   elem (r, c) at buf[(r>>2)*1024 + c*4 + (r&3)]
// Split-K=4 matvec: thread (oc in [0,128), q in [0,4)) owns cols {oc, oc+128},
// all 8 rows, i in [q*64, q*64+64). Combine: thread owns float4 at tid*4.

// main accumulation, fp16 weights: 16 coalesced LDG.128 per thread
__device__ __forceinline__ float4 mv4h_main(const __half* __restrict__ WT,
                                            const float* __restrict__ bias,
                                            const float* __restrict__ inT,
                                            float* __restrict__ Pp,
                                            int oc, int q, int tid)
{
    const float4* in4 = (const float4*)inT;
    const float4* wvp = (const float4*)WT + q*16*128 + oc;
    ull a00=0,a01=0,a02=0,a03=0;
    ull a10=0,a11=0,a12=0,a13=0;
#pragma unroll
    for (int jj = 0; jj < 16; jj++) {
        float4 wq = __ldg(wvp + jj*128);
        const __half2* wh = (const __half2*)&wq;   // wh[par] = (w_parA, w_parB)
#pragma unroll
        for (int par = 0; par < 4; par++) {
            int i = q*64 + jj*4 + par;
            float2 w = __half22float2(wh[par]);
            float4 u0 = in4[i];
            float4 u1 = in4[256 + i];
            ull p0 = pack2(u0.x,u0.y), p1 = pack2(u0.z,u0.w);
            ull p2 = pack2(u1.x,u1.y), p3 = pack2(u1.z,u1.w);
            ull wx = pack2(w.x,w.x), wy = pack2(w.y,w.y);
            fma2(a00,p0,wx); fma2(a01,p1,wx); fma2(a02,p2,wx); fma2(a03,p3,wx);
            fma2(a10,p0,wy); fma2(a11,p1,wy); fma2(a12,p2,wy); fma2(a13,p3,wy);
        }
    }
    float* P = Pp + q*2048;
    float f0,f1,f2,f3;
    unpack2(a00,f0,f1); unpack2(a01,f2,f3); *(float4*)(P + oc*4)        = make_float4(f0,f1,f2,f3);
    unpack2(a10,f0,f1); unpack2(a11,f2,f3); *(float4*)(P + 512 + oc*4)  = make_float4(f0,f1,f2,f3);
    unpack2(a02,f0,f1); unpack2(a03,f2,f3); *(float4*)(P + 1024 + oc*4) = make_float4(f0,f1,f2,f3);
    unpack2(a12,f0,f1); unpack2(a13,f2,f3); *(float4*)(P + 1536 + oc*4) = make_float4(f0,f1,f2,f3);
    __syncthreads();
    const int e4 = tid*4;
    float4 s0 = *(float4*)(Pp + e4);
    float4 s1 = *(float4*)(Pp + 2048 + e4);
    float4 s2 = *(float4*)(Pp + 4096 + e4);
    float4 s3 = *(float4*)(Pp + 6144 + e4);
    float b = __ldg(bias + (tid & 255));
    return make_float4(s0.x+s1.x+s2.x+s3.x+b, s0.y+s1.y+s2.y+s3.y+b,
                       s0.z+s1.z+s2.z+s3.z+b, s0.w+s1.w+s2.w+s3.w+b);
}

// plain layer (selu) -> outT
__device__ __noinline__ void mv4h_selu(const __half* __restrict__ WT,
                                       const float* __restrict__ bias,
                                       const float* __restrict__ inT,
                                       float* __restrict__ outT,
                                       float* __restrict__ Pp,
                                       int oc, int q, int tid)
{
    float4 v = mv4h_main(WT, bias, inT, Pp, oc, q, tid);
    v.x = selu_f(v.x); v.y = selu_f(v.y); v.z = selu_f(v.z); v.w = selu_f(v.w);
    *(float4*)(outT + tid*4) = v;
    __syncthreads();
}

// final ODE layer with fused stage epilogue. epi in [1,7].
__device__ __noinline__ void mv4h_last(const __half* __restrict__ WT,
                                       const float* __restrict__ bias,
                                       const float* __restrict__ inT,
                                       float* __restrict__ outT,
                                       float* __restrict__ sm,
                                       int oc, int q, int tid, int epi, float4 dv)
{
    float* Pp = sm + O_PP;
    float4 v = mv4h_main(WT, bias, inT, Pp, oc, q, tid);
    const int e4 = tid*4;
    *(float4*)(outT + e4) = v;
    float4 y = *(float4*)(sm + O_Y + e4);
#define PER4(DST, EX) do { float4 _o; _o.x=EX(x); _o.y=EX(y); _o.z=EX(z); _o.w=EX(w); \
                           *(float4*)(DST + e4) = _o; } while(0)
    if (epi == 1) {
#define S1(c) fmaf(dv.c, A21f*v.c, y.c)
        PER4(sm + O_TMP, S1);
#undef S1
    } else if (epi == 2) {
        float4 k1 = *(float4*)(sm + O_K1 + e4);
#define S2(c) fmaf(dv.c, A31f*k1.c + A32f*v.c, y.c)
        PER4(sm + O_TMP, S2);
#undef S2
    } else if (epi == 3) {
        float4 k1 = *(float4*)(sm + O_K1 + e4);
        float4 k2 = *(float4*)(sm + O_K2 + e4);
#define S3(c) fmaf(dv.c, A41f*k1.c + A42f*k2.c + A43f*v.c, y.c)
        PER4(sm + O_TMP, S3);
#undef S3
    } else if (epi == 4) {
        float4 k1 = *(float4*)(sm + O_K1 + e4);
        float4 k2 = *(float4*)(sm + O_K2 + e4);
        float4 k3 = *(float4*)(sm + O_K3 + e4);
#define S4(c) fmaf(dv.c, A51f*k1.c + A52f*k2.c + A53f*k3.c + A54f*v.c, y.c)
        PER4(sm + O_TMP, S4);
#undef S4
    } else if (epi == 5) {
        float4 k1 = *(float4*)(sm + O_K1 + e4);
        float4 k2 = *(float4*)(sm + O_K2 + e4);
        float4 k3 = *(float4*)(sm + O_K3 + e4);
        float4 k4 = *(float4*)(sm + O_K4 + e4);
#define S5(c) fmaf(dv.c, A61f*k1.c + A62f*k2.c + A63f*k3.c + A64f*k4.c + A65f*v.c, y.c)
        PER4(sm + O_TMP, S5);
#undef S5
    } else if (epi == 6) {
        float4 k1 = *(float4*)(sm + O_K1 + e4);
        float4 k3 = *(float4*)(sm + O_K3 + e4);
        float4 k4 = *(float4*)(sm + O_K4 + e4);
        float4 k5 = *(float4*)(sm + O_K5 + e4);
#define S6(c) fmaf(dv.c, BC0f*k1.c + BC2f*k3.c + BC3f*k4.c + BC4f*k5.c + BC5f*v.c, y.c)
        PER4(sm + O_Y5, S6);
#undef S6
    } else {   // epi == 7: error contributions -> red (== aT)
        float4 k1 = *(float4*)(sm + O_K1 + e4);
        float4 k3 = *(float4*)(sm + O_K3 + e4);
        float4 k4 = *(float4*)(sm + O_K4 + e4);
        float4 k5 = *(float4*)(sm + O_K5 + e4);
        float4 k6 = *(float4*)(sm + O_K6 + e4);
        float4 y5 = *(float4*)(sm + O_Y5 + e4);
#define S7(c) ({ float _e = EC0f*k1.c + EC2f*k3.c + EC3f*k4.c + EC4f*k5.c + EC5f*k6.c + EC6f*v.c; \
                 float _q = dv.c*_e / (1e-6f + 1e-3f*fmaxf(fabsf(y.c), fabsf(y5.c))); _q*_q; })
        PER4(sm + O_A, S7);
#undef S7
    }
#undef PER4
    __syncthreads();
}

__device__ __noinline__ void feval_fused(float* __restrict__ sm,
                                         const float* __restrict__ inT,
                                         float* __restrict__ outT,
                                         const float* ob1, const float* ob2,
                                         const float* ob3, const float* ob4,
                                         int oc, int q, int tid, int epi, float4 dv)
{
    float* Pp = sm + O_PP;
    mv4h_selu(g_oWHv[0], ob1, inT, sm + O_A, Pp, oc, q, tid);
    mv4h_selu(g_oWHv[1], ob2, sm + O_A, sm + O_B, Pp, oc, q, tid);
    mv4h_selu(g_oWHv[2], ob3, sm + O_B, sm + O_A, Pp, oc, q, tid);
    mv4h_last(g_oWHv[3], ob4, sm + O_A, outT, sm, oc, q, tid, epi, dv);
}

// fp32-weight matvec (encoder), act: 0 none, 2 relu
__device__ __noinline__ void mv4f(const float* __restrict__ WT,
                                  const float* __restrict__ bias,
                                  const float* __restrict__ inT,
                                  float* __restrict__ outT,
                                  float* __restrict__ Pp,
                                  int oc, int q, int tid, int act)
{
    const float4* in4 = (const float4*)inT;
    const float2* w2p = (const float2*)WT + q*64*128 + oc;
    ull a00=0,a01=0,a02=0,a03=0;
    ull a10=0,a11=0,a12=0,a13=0;
#pragma unroll 8
    for (int ii = 0; ii < 64; ii++) {
        int i = q*64 + ii;
        float2 w = __ldg(w2p + ii*128);
        float4 u0 = in4[i];
        float4 u1 = in4[256 + i];
        ull p0 = pack2(u0.x,u0.y), p1 = pack2(u0.z,u0.w);
        ull p2 = pack2(u1.x,u1.y), p3 = pack2(u1.z,u1.w);
        ull wx = pack2(w.x,w.x), wy = pack2(w.y,w.y);
        fma2(a00,p0,wx); fma2(a01,p1,wx); fma2(a02,p2,wx); fma2(a03,p3,wx);
        fma2(a10,p0,wy); fma2(a11,p1,wy); fma2(a12,p2,wy); fma2(a13,p3,wy);
    }
    float* P = Pp + q*2048;
    float f0,f1,f2,f3;
    unpack2(a00,f0,f1); unpack2(a01,f2,f3); *(float4*)(P + oc*4)        = make_float4(f0,f1,f2,f3);
    unpack2(a10,f0,f1); unpack2(a11,f2,f3); *(float4*)(P + 512 + oc*4)  = make_float4(f0,f1,f2,f3);
    unpack2(a02,f0,f1); unpack2(a03,f2,f3); *(float4*)(P + 1024 + oc*4) = make_float4(f0,f1,f2,f3);
    unpack2(a12,f0,f1); unpack2(a13,f2,f3); *(float4*)(P + 1536 + oc*4) = make_float4(f0,f1,f2,f3);
    __syncthreads();
    const int e4 = tid*4;
    float4 s0 = *(float4*)(Pp + e4);
    float4 s1 = *(float4*)(Pp + 2048 + e4);
    float4 s2 = *(float4*)(Pp + 4096 + e4);
    float4 s3 = *(float4*)(Pp + 6144 + e4);
    float b = __ldg(bias + (tid & 255));
    float4 v = make_float4(s0.x+s1.x+s2.x+s3.x+b, s0.y+s1.y+s2.y+s3.y+b,
                           s0.z+s1.z+s2.z+s3.z+b, s0.w+s1.w+s2.w+s3.w+b);
    if (act == 2) { v.x=fmaxf(v.x,0.f); v.y=fmaxf(v.y,0.f); v.z=fmaxf(v.z,0.f); v.w=fmaxf(v.w,0.f); }
    *(float4*)(outT + e4) = v;
    __syncthreads();
}

// ---------------- main persistent kernel ----------------
__global__ __launch_bounds__(NTH, 1)
void node_kernel(const float* __restrict__ x,     const float* __restrict__ meta,
                 const float* __restrict__ eps,   const float* __restrict__ times,
                 const float* __restrict__ doses,
                 const float* __restrict__ gbih,  const float* __restrict__ gbhh,
                 const float* __restrict__ eb1,   const float* __restrict__ eb2,
                 const float* __restrict__ ob1,   const float* __restrict__ ob2,
                 const float* __restrict__ ob3,   const float* __restrict__ ob4,
                 const float* __restrict__ fcW,   const float* __restrict__ fcb,
                 float* __restrict__ out)
{
    extern __shared__ float sm[];
    float* yT   = sm + O_Y;
    float* tmpT = sm + O_TMP;
    float* red  = sm + O_A;      // aT doubles as error buffer
    float* y5T  = sm + O_Y5;
    float* k1T  = sm + O_K1;     // x cache during GRU
    float* Pp   = sm + O_PP;     // split-K partials / GRU gate planes
    float* xc   = k1T;

    __shared__ float t_s[8], t1_s[8], dt_s[8], d_s[8], ds_s[8], meta_s[32];
    __shared__ int   act_s[8], accfl[8];

    const int tid  = threadIdx.x;
    const int oc   = tid & 127;      // ODE: column pair {oc, oc+128}
    const int q    = tid >> 7;       // ODE: K-chunk 0..3
    const int o    = tid & 255;      // GRU: column
    const int qg   = tid >> 8;       // GRU: 0 -> r,z ; 1 -> n
    const int wid  = tid >> 5;
    const int lane = tid & 31;
    const int r0   = blockIdx.x * RPB;
    const int e4   = tid*4;          // my float4 in [0,2048)
    const int hh   = tid >> 8;       // my row block: rows 4hh..4hh+3
    const int rb   = hh*4;

    for (int e = tid; e < 2048; e += NTH) { xc[e] = x[r0*256 + e]; yT[e] = 0.f; }
    if (tid < 32) meta_s[tid] = meta[r0*4 + tid];

    // GRU register weights / biases
    float wA[8], wB[8];
    float bA, bB, bN = 0.f;
    if (qg == 0) {
#pragma unroll
        for (int c = 0; c < 8; c++) { wA[c] = g_WihT[c*768 + o]; wB[c] = g_WihT[c*768 + o + 256]; }
        bA = gbih[o] + gbhh[o];
        bB = gbih[o+256] + gbhh[o+256];
    } else {
#pragma unroll
        for (int c = 0; c < 8; c++) { wA[c] = g_WihT[c*768 + o + 512]; wB[c] = 0.f; }
        bA = gbhh[o + 512];
        bN = gbih[o + 512];
        bB = 0.f;
    }
    __syncthreads();

    // ---------------- Phase A: GRU over 64 timesteps ----------------
    for (int t = 0; t < 64; t++) {
        if (qg == 0) {
            ull ar0 = pack2(bA,bA), ar1 = ar0, ar2 = ar0, ar3 = ar0;
            ull az0 = pack2(bB,bB), az1 = az0, az2 = az0, az3 = az0;
            const float2* wrz = (const float2*)g_WrzT + o;
            const float4* h4 = (const float4*)yT;
#pragma unroll 8
            for (int i = 0; i < 256; i++) {
                float2 w = __ldg(wrz + i*256);
                float4 u0 = h4[i];
                float4 u1 = h4[256 + i];
                ull p0 = pack2(u0.x,u0.y), p1 = pack2(u0.z,u0.w);
                ull p2 = pack2(u1.x,u1.y), p3 = pack2(u1.z,u1.w);
                ull wx = pack2(w.x,w.x), wy = pack2(w.y,w.y);
                fma2(ar0,p0,wx); fma2(ar1,p1,wx); fma2(ar2,p2,wx); fma2(ar3,p3,wx);
                fma2(az0,p0,wy); fma2(az1,p1,wy); fma2(az2,p2,wy); fma2(az3,p3,wy);
            }
            float fr[8], fz[8];
            unpack2(ar0,fr[0],fr[1]); unpack2(ar1,fr[2],fr[3]);
            unpack2(ar2,fr[4],fr[5]); unpack2(ar3,fr[6],fr[7]);
            unpack2(az0,fz[0],fz[1]); unpack2(az1,fz[2],fz[3]);
            unpack2(az2,fz[4],fz[5]); unpack2(az3,fz[6],fz[7]);
#pragma unroll
            for (int r = 0; r < 8; r++) {
                float sr = 0.f, sz = 0.f;
#pragma unroll
                for (int c = 0; c < 4; c++) {
                    float xv = xc[r*256 + t*4 + c];
                    sr = fmaf(xv, wA[c], sr); sz = fmaf(xv, wB[c], sz);
                }
#pragma unroll
                for (int c = 0; c < 4; c++) {
                    float mv = meta_s[r*4 + c];
                    sr = fmaf(mv, wA[4+c], sr); sz = fmaf(mv, wB[4+c], sz);
                }
                fr[r] = sigmoid_f(fr[r] + sr);
                fz[r] = sigmoid_f(fz[r] + sz);
            }
            *(float4*)(Pp + o*4)        = make_float4(fr[0],fr[1],fr[2],fr[3]);
            *(float4*)(Pp + 1024 + o*4) = make_float4(fr[4],fr[5],fr[6],fr[7]);
            *(float4*)(Pp + 2048 + o*4) = make_float4(fz[0],fz[1],fz[2],fz[3]);
            *(float4*)(Pp + 3072 + o*4) = make_float4(fz[4],fz[5],fz[6],fz[7]);
            __syncthreads();
            __syncthreads();
        } else {
            ull an0 = pack2(bA,bA), an1 = an0, an2 = an0, an3 = an0;
            const float* wn = g_WnT + o;
            const float4* h4 = (const float4*)yT;
#pragma unroll 8
            for (int i = 0; i < 256; i++) {
                float w = __ldg(wn + i*256);
                float4 u0 = h4[i];
                float4 u1 = h4[256 + i];
                ull w2 = pack2(w,w);
                fma2(an0, pack2(u0.x,u0.y), w2);
                fma2(an1, pack2(u0.z,u0.w), w2);
                fma2(an2, pack2(u1.x,u1.y), w2);
                fma2(an3, pack2(u1.z,u1.w), w2);
            }
            float hn[8];
            unpack2(an0,hn[0],hn[1]); unpack2(an1,hn[2],hn[3]);
            unpack2(an2,hn[4],hn[5]); unpack2(an3,hn[6],hn[7]);
            float inn[8];
#pragma unroll
            for (int r = 0; r < 8; r++) {
                float s = bN;
#pragma unroll
                for (int c = 0; c < 4; c++) s = fmaf(xc[r*256 + t*4 + c], wA[c], s);
#pragma unroll
                for (int c = 0; c < 4; c++) s = fmaf(meta_s[r*4 + c], wA[4+c], s);
                inn[r] = s;
            }
            __syncthreads();
            float4 R0 = *(float4*)(Pp + o*4);
            float4 R1 = *(float4*)(Pp + 1024 + o*4);
            float4 Z0 = *(float4*)(Pp + 2048 + o*4);
            float4 Z1 = *(float4*)(Pp + 3072 + o*4);
            float4 h0 = *(float4*)(yT + o*4);
            float4 h1 = *(float4*)(yT + 1024 + o*4);
            float Rr[8] = {R0.x,R0.y,R0.z,R0.w,R1.x,R1.y,R1.z,R1.w};
            float Zr[8] = {Z0.x,Z0.y,Z0.z,Z0.w,Z1.x,Z1.y,Z1.z,Z1.w};
            float hr[8] = {h0.x,h0.y,h0.z,h0.w,h1.x,h1.y,h1.z,h1.w};
            float hnew[8];
#pragma unroll
            for (int r = 0; r < 8; r++) {
                float n = tanhf(inn[r] + Rr[r]*hn[r]);
                hnew[r] = (1.f - Zr[r])*n + Zr[r]*hr[r];
            }
            *(float4*)(yT + o*4)        = make_float4(hnew[0],hnew[1],hnew[2],hnew[3]);
            *(float4*)(yT + 1024 + o*4) = make_float4(hnew[4],hnew[5],hnew[6],hnew[7]);
            __syncthreads();
        }
    }

    // ---------------- Phase B: encoder -> y0 ----------------
    mv4f(g_e1P,  eb1,       yT,          sm + O_B,  Pp, oc, q, tid, 2);  // relu
    mv4f(g_e2mP, eb2,       sm + O_B,    sm + O_A,  Pp, oc, q, tid, 0);  // mean
    mv4f(g_e2sP, eb2 + 256, sm + O_B,    y5T,       Pp, oc, q, tid, 0);  // std
    {
        int c = tid & 255;
        float4 m = *(float4*)(sm + O_A + e4);
        float4 s = *(float4*)(y5T + e4);
        float4 y0;
        y0.x = fmaf(__ldg(eps + (r0 + rb + 0)*256 + c), s.x, m.x);
        y0.y = fmaf(__ldg(eps + (r0 + rb + 1)*256 + c), s.y, m.y);
        y0.z = fmaf(__ldg(eps + (r0 + rb + 2)*256 + c), s.z, m.z);
        y0.w = fmaf(__ldg(eps + (r0 + rb + 3)*256 + c), s.w, m.w);
        *(float4*)(yT + e4) = y0;
    }
    __syncthreads();

    // ---------------- Phase C: 4 x dopri5 (FSAL + fused epilogues) --------
    for (int j = 0; j < 4; j++) {
        if (tid < 8) {
            int row = r0 + tid;
            float t0v = times[(j*1024 + row)*2 + 0];
            float t1v = times[(j*1024 + row)*2 + 1];
            t_s[tid]  = t0v;
            t1_s[tid] = t1v;
            dt_s[tid] = fmaxf(t1v - t0v, 1e-6f) * 0.1f;
            ds_s[tid] = (t0v < t1v) ? doses[j*1024 + row] : 0.f;
        }
        __syncthreads();
        {
            float4 y = *(float4*)(yT + e4);
            y.x += ds_s[rb+0]; y.y += ds_s[rb+1]; y.z += ds_s[rb+2]; y.w += ds_s[rb+3];
            *(float4*)(yT + e4) = y;
        }

        int fsal = 0;
        for (int step = 0; step < 32; step++) {
            int myact = 0;
            if (tid < 8) {
                float tt = t_s[tid], t1v = t1_s[tid];
                myact = (tt < t1v) ? 1 : 0;
                act_s[tid] = myact;
                float rem = fmaxf(t1v - tt, 0.f);
                d_s[tid] = fminf(fmaxf(dt_s[tid], 0.f), rem);
            }
            if (!__syncthreads_or(myact)) break;   // uniform exit

            const float4 dv = make_float4(d_s[rb+0], d_s[rb+1], d_s[rb+2], d_s[rb+3]);

            if (fsal) {
                // k1 select (exact FSAL) + stage-1 combine
                float4 kp  = *(float4*)(k1T + e4);
                float4 k7v = *(float4*)(tmpT + e4);
                if (accfl[rb+0]) kp.x = k7v.x;
                if (accfl[rb+1]) kp.y = k7v.y;
                if (accfl[rb+2]) kp.z = k7v.z;
                if (accfl[rb+3]) kp.w = k7v.w;
                *(float4*)(k1T + e4) = kp;
                float4 y = *(float4*)(yT + e4);
                float4 tt;
                tt.x = fmaf(dv.x, A21f*kp.x, y.x);
                tt.y = fmaf(dv.y, A21f*kp.y, y.y);
                tt.z = fmaf(dv.z, A21f*kp.z, y.z);
                tt.w = fmaf(dv.w, A21f*kp.w, y.w);
                *(float4*)(tmpT + e4) = tt;
                __syncthreads();
            } else {
                feval_fused(sm, yT, k1T, ob1, ob2, ob3, ob4, oc, q, tid, 1, dv);
            }
            feval_fused(sm, tmpT, sm + O_K2, ob1, ob2, ob3, ob4, oc, q, tid, 2, dv);
            feval_fused(sm, tmpT, sm + O_K3, ob1, ob2, ob3, ob4, oc, q, tid, 3, dv);
            feval_fused(sm, tmpT, sm + O_K4, ob1, ob2, ob3, ob4, oc, q, tid, 4, dv);
            feval_fused(sm, tmpT, sm + O_K5, ob1, ob2, ob3, ob4, oc, q, tid, 5, dv);
            feval_fused(sm, tmpT, sm + O_K6, ob1, ob2, ob3, ob4, oc, q, tid, 6, dv);  // -> y5T
            feval_fused(sm, y5T,  tmpT,     ob1, ob2, ob3, ob4, oc, q, tid, 7, dv);  // k7 + err->red

            if (wid < 8) {
                int r = wid;
                const float* rp = red + ((r>>2)<<10) + (r&3);
                float s = 0.f;
#pragma unroll
                for (int c = 0; c < 8; c++) s += rp[(lane + 32*c)*4];
                s += __shfl_xor_sync(0xffffffffu, s, 16);
                s += __shfl_xor_sync(0xffffffffu, s, 8);
                s += __shfl_xor_sync(0xffffffffu, s, 4);
                s += __shfl_xor_sync(0xffffffffu, s, 2);
                s += __shfl_xor_sync(0xffffffffu, s, 1);
                if (lane == 0) {
                    float en = sqrtf(s * (1.f/256.f));
                    int active = act_s[r];
                    int acc = (en <= 1.f) && active;
                    accfl[r] = acc;
                    float dtc = d_s[r];
                    if (acc) t_s[r] += dtc;
                    if (active) {
                        float fac = 0.9f * __expf(-0.2f * __logf(en + 1e-10f));
                        fac = fminf(fmaxf(fac, 0.2f), 10.f);
                        dt_s[r] = fmaxf(dtc, 1e-8f) * fac;
                    }
                }
            }
            __syncthreads();
            {
                float4 y  = *(float4*)(yT + e4);
                float4 y5 = *(float4*)(y5T + e4);
                if (accfl[rb+0]) y.x = y5.x;
                if (accfl[rb+1]) y.y = y5.y;
                if (accfl[rb+2]) y.z = y5.z;
                if (accfl[rb+3]) y.w = y5.w;
                *(float4*)(yT + e4) = y;
            }
            __syncthreads();
            fsal = 1;
        }
    }

    // ---------------- Phase D: linear head ----------------
    {
        float fcw = __ldg(fcW + (tid & 255));
        float4 y = *(float4*)(yT + e4);
        *(float4*)(red + e4) = make_float4(y.x*fcw, y.y*fcw, y.z*fcw, y.w*fcw);
        __syncthreads();
        if (wid < 8) {
            int r = wid;
            const float* rp = red + ((r>>2)<<10) + (r&3);
            float s = 0.f;
#pragma unroll
            for (int c = 0; c < 8; c++) s += rp[(lane + 32*c)*4];
            s += __shfl_xor_sync(0xffffffffu, s, 16);
            s += __shfl_xor_sync(0xffffffffu, s, 8);
            s += __shfl_xor_sync(0xffffffffu, s, 4);
            s += __shfl_xor_sync(0xffffffffu, s, 2);
            s += __shfl_xor_sync(0xffffffffu, s, 1);
            if (lane == 0) {
                s += fcb[0];
#pragma unroll
                for (int c = 0; c < 4; c++) s += meta_s[r*4 + c] * fcW[256 + c];
                out[r0 + r] = s;
            }
        }
    }
}

extern "C" void kernel_launch(void* const* d_in, const int* in_sizes, int n_in,
                              void* d_out, int out_size)
{
    const float* x     = (const float*)d_in[0];
    const float* meta  = (const float*)d_in[1];
    const float* eps   = (const float*)d_in[2];
    const float* times = (const float*)d_in[3];
    const float* doses = (const float*)d_in[4];
    const float* gWih  = (const float*)d_in[5];
    const float* gWhh  = (const float*)d_in[6];
    const float* gbih  = (const float*)d_in[7];
    const float* gbhh  = (const float*)d_in[8];
    const float* eW1   = (const float*)d_in[9];
    const float* eb1   = (const float*)d_in[10];
    const float* eW2   = (const float*)d_in[11];
    const float* eb2   = (const float*)d_in[12];
    const float* oW1   = (const float*)d_in[13];
    const float* ob1   = (const float*)d_in[14];
    const float* oW2   = (const float*)d_in[15];
    const float* ob2   = (const float*)d_in[16];
    const float* oW3   = (const float*)d_in[17];
    const float* ob3   = (const float*)d_in[18];
    const float* oW4   = (const float*)d_in[19];
    const float* ob4   = (const float*)d_in[20];
    const float* fcW   = (const float*)d_in[21];
    const float* fcb   = (const float*)d_in[22];
    float* out = (float*)d_out;

    prep_kernel<<<256, 256>>>(gWih, gWhh, eW1, eW2, oW1, oW2, oW3, oW4);

    const int smem_bytes = (11*2048 + 4*2048) * sizeof(float);   // 122880
    static int attr_done = 0;
    if (!attr_done) {
        cudaFuncSetAttribute(node_kernel, cudaFuncAttributeMaxDynamicSharedMemorySize, smem_bytes);
        attr_done = 1;
    }
    node_kernel<<<128, NTH, smem_bytes>>>(x, meta, eps, times, doses,
                                          gbih, gbhh, eb1, eb2,
                                          ob1, ob2, ob3, ob4, fcW, fcb, out);
}